// round 4
// baseline (speedup 1.0000x reference)
#include <cuda_runtime.h>

// 5x5 median filter, reflect padding, [16,3,256,256] fp32.
//
// Per thread: 2 horizontally-adjacent output pixels (PPT=2 keeps regs <=64
// for 50% occupancy).
//  - sort 6 shared columns (9-CAS sort5) on the FMA pipe (4-op arithmetic CAS)
//  - per pixel: rank-row SET selection; mid3 on FMA pipe, rest on ALU (FMNMX)
//  - forgetful selection of rank-7-of-13 with tree minmax (ALU)
// ~134 alu ops + ~132 fma ops per pixel: both rt=2 pipes balanced.

#define BX 32
#define BY 8
#define PPT 2
#define OUT_W (BX * PPT)        // 64
#define OUT_H BY                // 8
#define PAD 2
#define TILE_W (OUT_W + 2*PAD)  // 68
#define TILE_H (OUT_H + 2*PAD)  // 12
#define IMG 256

// ALU-pipe CAS (2x FMNMX).
__device__ __forceinline__ void cas(float& a, float& b) {
    float lo = fminf(a, b);
    float hi = fmaxf(a, b);
    a = lo;
    b = hi;
}

// FMA-pipe CAS: 4 ops (FADD/FADD/FADD.withabs/FMUL), |d| is a free operand mod.
// hi = (a+b+|a-b|)/2 = max, lo = (a+b) - hi = min.  Exact to ~1 ulp on [0,1).
__device__ __forceinline__ void cas_fma(float& a, float& b) {
    float d = a - b;
    float s = a + b;
    float hi = (s + fabsf(d)) * 0.5f;
    float lo = s - hi;
    a = lo;
    b = hi;
}

// Optimal 9-CAS sorting network for 5 elements, FMA pipe.
__device__ __forceinline__ void sort5_fma(float& a, float& b, float& c, float& d, float& e) {
    cas_fma(a, b); cas_fma(d, e); cas_fma(c, e); cas_fma(c, d); cas_fma(b, e);
    cas_fma(a, d); cas_fma(a, c); cas_fma(b, d); cas_fma(b, c);
}

__device__ __forceinline__ int reflect_idx(int i, int n) {
    i = (i < 0) ? -i : i;
    i = (i >= n) ? (2 * n - 2 - i) : i;
    return i;
}

__global__ __launch_bounds__(BX * BY, 4) void median5_kernel(
    const float* __restrict__ in, float* __restrict__ out) {
    __shared__ float tile[TILE_H][TILE_W];

    const int plane = blockIdx.z;  // 48 planes
    const float* src = in + (size_t)plane * IMG * IMG;
    float* dst = out + (size_t)plane * IMG * IMG;

    const int bx = blockIdx.x * OUT_W;
    const int by = blockIdx.y * OUT_H;
    const int tid = threadIdx.y * BX + threadIdx.x;

    // Cooperative halo tile load with reflect padding (816 elems, 256 thr).
    #pragma unroll
    for (int i = tid; i < TILE_H * TILE_W; i += BX * BY) {
        int r = i / TILE_W;
        int c = i - r * TILE_W;
        int gy = reflect_idx(by + r - PAD, IMG);
        int gx = reflect_idx(bx + c - PAD, IMG);
        tile[r][c] = src[gy * IMG + gx];
    }
    __syncthreads();

    // Load 6 columns x 5 rows via three float2 loads per row (8B aligned:
    // row stride 68 floats, col offset 2*tx floats).
    float col[6][5];
    #pragma unroll
    for (int r = 0; r < 5; r++) {
        const float2* rp =
            reinterpret_cast<const float2*>(&tile[threadIdx.y + r][threadIdx.x * PPT]);
        float2 v0 = rp[0];
        float2 v1 = rp[1];
        float2 v2 = rp[2];
        col[0][r] = v0.x; col[1][r] = v0.y;
        col[2][r] = v1.x; col[3][r] = v1.y;
        col[4][r] = v2.x; col[5][r] = v2.y;
    }
    #pragma unroll
    for (int j = 0; j < 6; j++)
        sort5_fma(col[j][0], col[j][1], col[j][2], col[j][3], col[j][4]);

    float results[PPT];
    #pragma unroll
    for (int p = 0; p < PPT; p++) {
        float a, b, c, d, e;

        // Row 0 (column minima): need set of 2 largest. (ALU)
        a = col[p][0]; b = col[p+1][0]; c = col[p+2][0]; d = col[p+3][0]; e = col[p+4][0];
        cas(a, b); cas(c, d); cas(b, d); cas(d, e);   // e = max5
        cas(a, b); cas(c, d); cas(b, d);              // d = 2nd max
        float w0 = e, w1 = d;

        // Row 1: need set of 3 largest (remove bottom-2). (ALU)
        a = col[p][1]; b = col[p+1][1]; c = col[p+2][1]; d = col[p+3][1]; e = col[p+4][1];
        cas(a, b); cas(c, d); cas(a, c); cas(a, e);   // a = min5
        cas(b, c); cas(d, e); cas(b, d);              // b = 2nd min
        float w2 = c, w3 = d, w4 = e;

        // Row 2 (column medians): need middle-3 set. (FMA pipe)
        a = col[p][2]; b = col[p+1][2]; c = col[p+2][2]; d = col[p+3][2]; e = col[p+4][2];
        cas_fma(a, b); cas_fma(c, d); cas_fma(a, c);
        cas_fma(b, d); cas_fma(a, e); cas_fma(e, d);
        float w5 = b, w6 = c, w7 = e;                 // a = min5, d = max5

        // Row 3: need set of 3 smallest (remove top-2). (ALU)
        a = col[p][3]; b = col[p+1][3]; c = col[p+2][3]; d = col[p+3][3]; e = col[p+4][3];
        cas(a, b); cas(c, d); cas(b, d); cas(d, e);   // e = max5
        cas(a, b); cas(c, d); cas(b, d);              // d = 2nd max
        float s0 = a, s1 = b, s2 = c;

        // Row 4 (column maxima): need set of 2 smallest. (ALU)
        a = col[p][4]; b = col[p+1][4]; c = col[p+2][4]; d = col[p+3][4]; e = col[p+4][4];
        cas(a, b); cas(c, d); cas(a, c); cas(a, e);   // a = min5
        cas(b, c); cas(d, e); cas(b, d);              // b = 2nd min
        float s3 = a, s4 = b;

        // Forgetful selection: median = rank 7 (1-indexed) of the 13 candidates. (ALU)
        // minmax8 (tree): w0 = min, w7 = max, survivors w1..w6.
        cas(w0, w1); cas(w2, w3); cas(w4, w5); cas(w6, w7);
        cas(w0, w2); cas(w4, w6); cas(w0, w4);
        cas(w1, w3); cas(w5, w7); cas(w3, w7);
        w0 = s0;
        // minmax7: w0 = min, w6 = max, survivors w1..w5.
        cas(w0, w1); cas(w2, w3); cas(w4, w5);
        cas(w0, w2); cas(w4, w6); cas(w0, w4);
        cas(w1, w3); cas(w5, w6); cas(w3, w6);
        w0 = s1;
        // minmax6: w0 = min, w5 = max, survivors w1..w4.
        cas(w0, w1); cas(w2, w3); cas(w4, w5);
        cas(w0, w2); cas(w0, w4);
        cas(w1, w3); cas(w3, w5);
        w0 = s2;
        // minmax5: w0 = min, w3 = max, survivors w1, w2, w4.
        cas(w0, w1); cas(w2, w3); cas(w0, w2); cas(w1, w3); cas(w0, w4); cas(w4, w3);
        w0 = s3;
        // minmax4 on (w0, w1, w2, w4): w0 = min, w4 = max, survivors w1, w2.
        cas(w0, w1); cas(w2, w4); cas(w0, w2); cas(w1, w4);
        w0 = s4;
        // median of 3 -> w1.
        cas(w0, w1); cas(w1, w2); cas(w0, w1);

        results[p] = w1;
    }

    const int gy = by + threadIdx.y;
    float2 r2 = make_float2(results[0], results[1]);
    *reinterpret_cast<float2*>(&dst[gy * IMG + bx + threadIdx.x * PPT]) = r2;
}

extern "C" void kernel_launch(void* const* d_in, const int* in_sizes, int n_in,
                              void* d_out, int out_size) {
    const float* image = (const float*)d_in[0];
    float* out = (float*)d_out;
    (void)in_sizes; (void)n_in; (void)out_size;

    dim3 block(BX, BY);
    dim3 grid(IMG / OUT_W, IMG / OUT_H, 16 * 3);
    median5_kernel<<<grid, block>>>(image, out);
}

// round 5
// speedup vs baseline: 1.5970x; 1.5970x over previous
#include <cuda_runtime.h>
#include <cuda_fp16.h>

// 5x5 median filter, reflect padding, [16,3,256,256] fp32.
//
// fp16x2 packed median: each half2 CAS (HMNMX2 pair) processes 2 pixels.
// Stride-2 packing C[k] = (col k, col k+2) preserves sorted-column reuse:
// pixel pair (p, p+2) consumes packed columns C[p..p+4].
// Per lane: 4 pixels = 2 packed pairs; 6 packed column sorts (9-CAS sort5)
// + per pair rank-row SET selection (34) + forgetful rank-7-of-13 (39).
// ~100 instructions/pixel vs 182 in the fp32 round-2 kernel.
// fp16 RN conversion error <= 2^-11 rel (<1e-3 threshold); min/max exact in fp16.

#define BX 16
#define BY 16
#define PPT 4
#define OUT_W (BX * PPT)        // 64
#define OUT_H BY                // 16
#define PAD 2
#define TILE_W (OUT_W + 2*PAD)  // 68
#define TILE_H (OUT_H + 2*PAD)  // 20
#define IMG 256

__device__ __forceinline__ void cas2(__half2& a, __half2& b) {
    __half2 lo = __hmin2(a, b);
    __half2 hi = __hmax2(a, b);
    a = lo;
    b = hi;
}

// Optimal 9-CAS sorting network for 5 elements (packed, 2 pixels at once).
__device__ __forceinline__ void sort5p(__half2& a, __half2& b, __half2& c,
                                       __half2& d, __half2& e) {
    cas2(a, b); cas2(d, e); cas2(c, e); cas2(c, d); cas2(b, e);
    cas2(a, d); cas2(a, c); cas2(b, d); cas2(b, c);
}

__device__ __forceinline__ int reflect_idx(int i, int n) {
    i = (i < 0) ? -i : i;
    i = (i >= n) ? (2 * n - 2 - i) : i;
    return i;
}

__global__ __launch_bounds__(BX * BY, 4) void median5_kernel(
    const float* __restrict__ in, float* __restrict__ out) {
    __shared__ float tile[TILE_H][TILE_W];

    const int plane = blockIdx.z;  // 48 planes
    const float* src = in + (size_t)plane * IMG * IMG;
    float* dst = out + (size_t)plane * IMG * IMG;

    const int bx = blockIdx.x * OUT_W;
    const int by = blockIdx.y * OUT_H;
    const int tid = threadIdx.y * BX + threadIdx.x;

    // Cooperative halo tile load with reflect padding.
    #pragma unroll
    for (int i = tid; i < TILE_H * TILE_W; i += BX * BY) {
        int r = i / TILE_W;
        int c = i - r * TILE_W;
        int gy = reflect_idx(by + r - PAD, IMG);
        int gx = reflect_idx(bx + c - PAD, IMG);
        tile[r][c] = src[gy * IMG + gx];
    }
    __syncthreads();

    // Read 8 fp32 columns x 5 rows (two float4 loads per row, 16B aligned),
    // pack into 6 stride-2 half2 columns: C[k] = (col k, col k+2).
    __half2 col[6][5];
    #pragma unroll
    for (int r = 0; r < 5; r++) {
        const float4* rp =
            reinterpret_cast<const float4*>(&tile[threadIdx.y + r][threadIdx.x * PPT]);
        float4 lo = rp[0];
        float4 hi = rp[1];
        float t[8] = {lo.x, lo.y, lo.z, lo.w, hi.x, hi.y, hi.z, hi.w};
        #pragma unroll
        for (int k = 0; k < 6; k++)
            col[k][r] = __floats2half2_rn(t[k], t[k + 2]);
    }
    #pragma unroll
    for (int k = 0; k < 6; k++)
        sort5p(col[k][0], col[k][1], col[k][2], col[k][3], col[k][4]);

    // Pair g handles pixels (4*tx + g) [.x halves] and (4*tx + g + 2) [.y halves],
    // consuming packed columns col[g .. g+4].
    __half2 res[2];
    #pragma unroll
    for (int g = 0; g < 2; g++) {
        __half2 a, b, c, d, e;

        // Row 0 (column minima): need set of 2 largest.
        a = col[g][0]; b = col[g+1][0]; c = col[g+2][0]; d = col[g+3][0]; e = col[g+4][0];
        cas2(a, b); cas2(c, d); cas2(b, d); cas2(d, e);   // e = max5
        cas2(a, b); cas2(c, d); cas2(b, d);               // d = 2nd max
        __half2 w0 = e, w1 = d;

        // Row 1: need set of 3 largest (remove bottom-2).
        a = col[g][1]; b = col[g+1][1]; c = col[g+2][1]; d = col[g+3][1]; e = col[g+4][1];
        cas2(a, b); cas2(c, d); cas2(a, c); cas2(a, e);   // a = min5
        cas2(b, c); cas2(d, e); cas2(b, d);               // b = 2nd min
        __half2 w2 = c, w3 = d, w4 = e;

        // Row 2 (column medians): need middle-3 set (strip min and max).
        a = col[g][2]; b = col[g+1][2]; c = col[g+2][2]; d = col[g+3][2]; e = col[g+4][2];
        cas2(a, b); cas2(c, d); cas2(a, c); cas2(b, d); cas2(a, e); cas2(e, d);
        __half2 w5 = b, w6 = c, w7 = e;                   // a = min5, d = max5

        // Row 3: need set of 3 smallest (remove top-2).
        a = col[g][3]; b = col[g+1][3]; c = col[g+2][3]; d = col[g+3][3]; e = col[g+4][3];
        cas2(a, b); cas2(c, d); cas2(b, d); cas2(d, e);   // e = max5
        cas2(a, b); cas2(c, d); cas2(b, d);               // d = 2nd max
        __half2 s0 = a, s1 = b, s2 = c;

        // Row 4 (column maxima): need set of 2 smallest.
        a = col[g][4]; b = col[g+1][4]; c = col[g+2][4]; d = col[g+3][4]; e = col[g+4][4];
        cas2(a, b); cas2(c, d); cas2(a, c); cas2(a, e);   // a = min5
        cas2(b, c); cas2(d, e); cas2(b, d);               // b = 2nd min
        __half2 s3 = a, s4 = b;

        // Forgetful selection: median = rank 7 (1-indexed) of the 13 candidates.
        // minmax8 (tree): w0 = min, w7 = max, survivors w1..w6.
        cas2(w0, w1); cas2(w2, w3); cas2(w4, w5); cas2(w6, w7);
        cas2(w0, w2); cas2(w4, w6); cas2(w0, w4);
        cas2(w1, w3); cas2(w5, w7); cas2(w3, w7);
        w0 = s0;
        // minmax7: w0 = min, w6 = max, survivors w1..w5.
        cas2(w0, w1); cas2(w2, w3); cas2(w4, w5);
        cas2(w0, w2); cas2(w4, w6); cas2(w0, w4);
        cas2(w1, w3); cas2(w5, w6); cas2(w3, w6);
        w0 = s1;
        // minmax6: w0 = min, w5 = max, survivors w1..w4.
        cas2(w0, w1); cas2(w2, w3); cas2(w4, w5);
        cas2(w0, w2); cas2(w0, w4);
        cas2(w1, w3); cas2(w3, w5);
        w0 = s2;
        // minmax5: w0 = min, w3 = max, survivors w1, w2, w4.
        cas2(w0, w1); cas2(w2, w3); cas2(w0, w2); cas2(w1, w3); cas2(w0, w4); cas2(w4, w3);
        w0 = s3;
        // minmax4 on (w0, w1, w2, w4): w0 = min, w4 = max, survivors w1, w2.
        cas2(w0, w1); cas2(w2, w4); cas2(w0, w2); cas2(w1, w4);
        w0 = s4;
        // median of 3 -> w1.
        cas2(w0, w1); cas2(w1, w2); cas2(w0, w1);

        res[g] = w1;
    }

    // Unpack: pair0 = pixels (0,2), pair1 = pixels (1,3).
    float2 p0 = __half22float2(res[0]);
    float2 p1 = __half22float2(res[1]);
    float4 r4 = make_float4(p0.x, p1.x, p0.y, p1.y);

    const int gy = by + threadIdx.y;
    *reinterpret_cast<float4*>(&dst[gy * IMG + bx + threadIdx.x * PPT]) = r4;
}

extern "C" void kernel_launch(void* const* d_in, const int* in_sizes, int n_in,
                              void* d_out, int out_size) {
    const float* image = (const float*)d_in[0];
    float* out = (float*)d_out;
    (void)in_sizes; (void)n_in; (void)out_size;

    dim3 block(BX, BY);
    dim3 grid(IMG / OUT_W, IMG / OUT_H, 16 * 3);
    median5_kernel<<<grid, block>>>(image, out);
}

// round 6
// speedup vs baseline: 1.7436x; 1.0918x over previous
#include <cuda_runtime.h>
#include <cuda_fp16.h>

// 5x5 median filter, reflect padding, [16,3,256,256] fp32.
//
// fp16x2 packed median (2 pixels per half2 lane), stride-2 packing:
// C[k] = (col k, col k+2); pair g uses packed columns C[g..g+4].
// Round-6: the two pairs per thread share packed cols 1..4, so each rank-row
// set-selection is computed once on the shared 4 and extended per-pair with
// 3 ops via exact tournament identities. ~330 packed ops/thread (83/px).

#define BX 16
#define BY 16
#define PPT 4
#define OUT_W (BX * PPT)        // 64
#define OUT_H BY                // 16
#define PAD 2
#define TILE_W (OUT_W + 2*PAD)  // 68
#define TILE_H (OUT_H + 2*PAD)  // 20
#define IMG 256

__device__ __forceinline__ void cas2(__half2& a, __half2& b) {
    __half2 lo = __hmin2(a, b);
    __half2 hi = __hmax2(a, b);
    a = lo;
    b = hi;
}

// Optimal 9-CAS sorting network for 5 elements (packed).
__device__ __forceinline__ void sort5p(__half2& a, __half2& b, __half2& c,
                                       __half2& d, __half2& e) {
    cas2(a, b); cas2(d, e); cas2(c, e); cas2(c, d); cas2(b, e);
    cas2(a, d); cas2(a, c); cas2(b, d); cas2(b, c);
}

__device__ __forceinline__ int reflect_idx(int i, int n) {
    i = (i < 0) ? -i : i;
    i = (i >= n) ? (2 * n - 2 - i) : i;
    return i;
}

__global__ __launch_bounds__(BX * BY, 5) void median5_kernel(
    const float* __restrict__ in, float* __restrict__ out) {
    __shared__ float tile[TILE_H][TILE_W];

    const int plane = blockIdx.z;  // 48 planes
    const float* src = in + (size_t)plane * IMG * IMG;
    float* dst = out + (size_t)plane * IMG * IMG;

    const int bx = blockIdx.x * OUT_W;
    const int by = blockIdx.y * OUT_H;
    const int tid = threadIdx.y * BX + threadIdx.x;

    // Cooperative halo tile load with reflect padding.
    #pragma unroll
    for (int i = tid; i < TILE_H * TILE_W; i += BX * BY) {
        int r = i / TILE_W;
        int c = i - r * TILE_W;
        int gy = reflect_idx(by + r - PAD, IMG);
        int gx = reflect_idx(bx + c - PAD, IMG);
        tile[r][c] = src[gy * IMG + gx];
    }
    __syncthreads();

    // Read 8 fp32 columns x 5 rows, pack into 6 stride-2 half2 columns.
    __half2 col[6][5];
    #pragma unroll
    for (int r = 0; r < 5; r++) {
        const float4* rp =
            reinterpret_cast<const float4*>(&tile[threadIdx.y + r][threadIdx.x * PPT]);
        float4 lo = rp[0];
        float4 hi = rp[1];
        float t[8] = {lo.x, lo.y, lo.z, lo.w, hi.x, hi.y, hi.z, hi.w};
        #pragma unroll
        for (int k = 0; k < 6; k++)
            col[k][r] = __floats2half2_rn(t[k], t[k + 2]);
    }
    #pragma unroll
    for (int k = 0; k < 6; k++)
        sort5p(col[k][0], col[k][1], col[k][2], col[k][3], col[k][4]);

    // Candidate sets for the two pairs (pair 0: cols 0..4, pair 1: cols 1..5).
    __half2 w[2][8], s[2][5];

    // ---- Row 0 (column minima): top-2 set of 5. ----
    {
        __half2 x1 = col[1][0], x2 = col[2][0], x3 = col[3][0], x4 = col[4][0];
        cas2(x1, x2); cas2(x3, x4);                       // x2,x4 highs; x1,x3 lows
        __half2 T1 = __hmax2(x2, x4);                     // max of shared 4
        __half2 T2 = __hmax2(__hmin2(x2, x4), __hmax2(x1, x3));  // 2nd of shared 4
        __half2 e0 = col[0][0], e1 = col[5][0];
        w[0][0] = __hmax2(T1, e0); w[0][1] = __hmax2(T2, __hmin2(T1, e0));
        w[1][0] = __hmax2(T1, e1); w[1][1] = __hmax2(T2, __hmin2(T1, e1));
    }
    // ---- Row 1: top-3 set of 5. ----
    {
        __half2 x1 = col[1][1], x2 = col[2][1], x3 = col[3][1], x4 = col[4][1];
        cas2(x1, x2); cas2(x3, x4);
        __half2 y  = __hmax2(x1, x3);                     // top3of4 = {x2, x4, y}
        __half2 mx = __hmax2(x2, x4), mn = __hmin2(x2, x4);
        __half2 e0 = col[0][1], e1 = col[5][1];
        // remove-min of {x2,x4,y,e} = {mx, max(y,e), max(mn, min(y,e))}
        w[0][2] = mx; w[0][3] = __hmax2(y, e0); w[0][4] = __hmax2(mn, __hmin2(y, e0));
        w[1][2] = mx; w[1][3] = __hmax2(y, e1); w[1][4] = __hmax2(mn, __hmin2(y, e1));
    }
    // ---- Row 2 (column medians): middle-3 set of 5. ----
    {
        __half2 x1 = col[1][2], x2 = col[2][2], x3 = col[3][2], x4 = col[4][2];
        cas2(x1, x2); cas2(x3, x4); cas2(x1, x3); cas2(x2, x4);
        // x1 = min4, x4 = max4, mids = {x2, x3}
        __half2 e0 = col[0][2], e1 = col[5][2];
        w[0][5] = x2; w[0][6] = x3; w[0][7] = __hmin2(__hmax2(x1, e0), x4);
        w[1][5] = x2; w[1][6] = x3; w[1][7] = __hmin2(__hmax2(x1, e1), x4);
    }
    // ---- Row 3: bottom-3 set of 5. ----
    {
        __half2 x1 = col[1][3], x2 = col[2][3], x3 = col[3][3], x4 = col[4][3];
        cas2(x1, x2); cas2(x3, x4);
        __half2 z = __hmin2(x2, x4);                      // bot3of4 = {x1, x3, z}
        __half2 m = __hmin2(x1, x3), M = __hmax2(x1, x3);
        __half2 e0 = col[0][3], e1 = col[5][3];
        // remove-max of {x1,x3,z,e} = {m, min(z,e), min(M, max(z,e))}
        s[0][0] = m; s[0][1] = __hmin2(z, e0); s[0][2] = __hmin2(M, __hmax2(z, e0));
        s[1][0] = m; s[1][1] = __hmin2(z, e1); s[1][2] = __hmin2(M, __hmax2(z, e1));
    }
    // ---- Row 4 (column maxima): bottom-2 set of 5. ----
    {
        __half2 x1 = col[1][4], x2 = col[2][4], x3 = col[3][4], x4 = col[4][4];
        cas2(x1, x2); cas2(x3, x4);
        __half2 B1 = __hmin2(x1, x3);                     // min of shared 4
        __half2 B2 = __hmin2(__hmax2(x1, x3), __hmin2(x2, x4));  // 2nd smallest
        __half2 e0 = col[0][4], e1 = col[5][4];
        s[0][3] = __hmin2(B1, e0); s[0][4] = __hmin2(B2, __hmax2(B1, e0));
        s[1][3] = __hmin2(B1, e1); s[1][4] = __hmin2(B2, __hmax2(B1, e1));
    }

    // Forgetful selection: median = rank 7 (1-indexed) of the 13 candidates.
    __half2 res[2];
    #pragma unroll
    for (int g = 0; g < 2; g++) {
        __half2 w0 = w[g][0], w1 = w[g][1], w2 = w[g][2], w3 = w[g][3];
        __half2 w4 = w[g][4], w5 = w[g][5], w6 = w[g][6], w7 = w[g][7];

        // minmax8 (tree): w0 = min, w7 = max, survivors w1..w6.
        cas2(w0, w1); cas2(w2, w3); cas2(w4, w5); cas2(w6, w7);
        cas2(w0, w2); cas2(w4, w6); cas2(w0, w4);
        cas2(w1, w3); cas2(w5, w7); cas2(w3, w7);
        w0 = s[g][0];
        // minmax7: survivors w1..w5.
        cas2(w0, w1); cas2(w2, w3); cas2(w4, w5);
        cas2(w0, w2); cas2(w4, w6); cas2(w0, w4);
        cas2(w1, w3); cas2(w5, w6); cas2(w3, w6);
        w0 = s[g][1];
        // minmax6: survivors w1..w4.
        cas2(w0, w1); cas2(w2, w3); cas2(w4, w5);
        cas2(w0, w2); cas2(w0, w4);
        cas2(w1, w3); cas2(w3, w5);
        w0 = s[g][2];
        // minmax5: survivors w1, w2, w4.
        cas2(w0, w1); cas2(w2, w3); cas2(w0, w2); cas2(w1, w3); cas2(w0, w4); cas2(w4, w3);
        w0 = s[g][3];
        // minmax4 on (w0, w1, w2, w4): survivors w1, w2.
        cas2(w0, w1); cas2(w2, w4); cas2(w0, w2); cas2(w1, w4);
        w0 = s[g][4];
        // median of 3 -> w1.
        cas2(w0, w1); cas2(w1, w2); cas2(w0, w1);

        res[g] = w1;
    }

    // Unpack: pair0 = pixels (0,2), pair1 = pixels (1,3).
    float2 p0 = __half22float2(res[0]);
    float2 p1 = __half22float2(res[1]);
    float4 r4 = make_float4(p0.x, p1.x, p0.y, p1.y);

    const int gy = by + threadIdx.y;
    *reinterpret_cast<float4*>(&dst[gy * IMG + bx + threadIdx.x * PPT]) = r4;
}

extern "C" void kernel_launch(void* const* d_in, const int* in_sizes, int n_in,
                              void* d_out, int out_size) {
    const float* image = (const float*)d_in[0];
    float* out = (float*)d_out;
    (void)in_sizes; (void)n_in; (void)out_size;

    dim3 block(BX, BY);
    dim3 grid(IMG / OUT_W, IMG / OUT_H, 16 * 3);
    median5_kernel<<<grid, block>>>(image, out);
}

// round 7
// speedup vs baseline: 1.7730x; 1.0169x over previous
#include <cuda_runtime.h>
#include <cuda_fp16.h>

// 5x5 median filter, reflect padding, [16,3,256,256] fp32.
//
// fp16x2 packed median (2 pixels per half2 lane), stride-2 packing:
// P[r][c] = (half v[c], half v[c+2]) built ONCE in the smem load phase.
// Pair g (pixels 4tx+g, 4tx+g+2) uses packed columns P[.][4tx+g .. 4tx+g+4].
// Shared-4 set selections + per-pair 3-op tournament extensions, then
// forgetful rank-7-of-13 (first CAS elided via known (2ndmax<=max) order,
// tail med3 via 4-op identity).

#define BX 16
#define BY 16
#define PPT 4
#define OUT_W (BX * PPT)        // 64
#define OUT_H BY                // 16
#define PAD 2
#define TILE_W (OUT_W + 2*PAD)  // 68 source columns
#define TILE_H (OUT_H + 2*PAD)  // 20
#define PROW 68                 // padded packed-row stride (272B = 17*16B)
#define IMG 256

__device__ __forceinline__ void cas2(__half2& a, __half2& b) {
    __half2 lo = __hmin2(a, b);
    __half2 hi = __hmax2(a, b);
    a = lo;
    b = hi;
}

// Optimal 9-CAS sorting network for 5 elements (packed).
__device__ __forceinline__ void sort5p(__half2& a, __half2& b, __half2& c,
                                       __half2& d, __half2& e) {
    cas2(a, b); cas2(d, e); cas2(c, e); cas2(c, d); cas2(b, e);
    cas2(a, d); cas2(a, c); cas2(b, d); cas2(b, c);
}

__device__ __forceinline__ int reflect_idx(int i, int n) {
    i = (i < 0) ? -i : i;
    i = (i >= n) ? (2 * n - 2 - i) : i;
    return i;
}

__global__ __launch_bounds__(BX * BY, 6) void median5_kernel(
    const float* __restrict__ in, float* __restrict__ out) {
    // Packed tile: P[r][c] = (half v[c], half v[c+2]); valid c = 0..65.
    __shared__ __half2 P[TILE_H][PROW];

    const int plane = blockIdx.z;  // 48 planes
    const float* src = in + (size_t)plane * IMG * IMG;
    float* dst = out + (size_t)plane * IMG * IMG;

    const int bx = blockIdx.x * OUT_W;
    const int by = blockIdx.y * OUT_H;
    const int tid = threadIdx.y * BX + threadIdx.x;

    // Load halo, convert fp32->fp16 once, scatter each half into the two
    // packed slots it belongs to: x-half of P[r][c], y-half of P[r][c-2].
    #pragma unroll
    for (int i = tid; i < TILE_H * TILE_W; i += BX * BY) {
        int r = i / TILE_W;
        int c = i - r * TILE_W;
        int gy = reflect_idx(by + r - PAD, IMG);
        int gx = reflect_idx(bx + c - PAD, IMG);
        __half h = __float2half_rn(src[gy * IMG + gx]);
        __half* base = reinterpret_cast<__half*>(&P[r][0]);
        if (c <= TILE_W - 3) base[2 * c] = h;          // x-half of P[r][c]
        if (c >= 2)          base[2 * (c - 2) + 1] = h; // y-half of P[r][c-2]
    }
    __syncthreads();

    // Read 6 packed columns x 5 rows (uint4 + uint2 LDS, 16B aligned).
    __half2 col[6][5];
    #pragma unroll
    for (int r = 0; r < 5; r++) {
        const __half2* rowp = &P[threadIdx.y + r][threadIdx.x * PPT];
        uint4 q = *reinterpret_cast<const uint4*>(rowp);
        uint2 q2 = *reinterpret_cast<const uint2*>(rowp + 4);
        col[0][r] = *reinterpret_cast<__half2*>(&q.x);
        col[1][r] = *reinterpret_cast<__half2*>(&q.y);
        col[2][r] = *reinterpret_cast<__half2*>(&q.z);
        col[3][r] = *reinterpret_cast<__half2*>(&q.w);
        col[4][r] = *reinterpret_cast<__half2*>(&q2.x);
        col[5][r] = *reinterpret_cast<__half2*>(&q2.y);
    }
    #pragma unroll
    for (int k = 0; k < 6; k++)
        sort5p(col[k][0], col[k][1], col[k][2], col[k][3], col[k][4]);

    // Candidate sets for the two pairs (pair 0: cols 0..4, pair 1: cols 1..5).
    __half2 w[2][8], s[2][5];

    // ---- Row 0 (column minima): top-2 set of 5; (w0,w1) = (2nd max, max). ----
    {
        __half2 x1 = col[1][0], x2 = col[2][0], x3 = col[3][0], x4 = col[4][0];
        cas2(x1, x2); cas2(x3, x4);
        __half2 T1 = __hmax2(x2, x4);
        __half2 T2 = __hmax2(__hmin2(x2, x4), __hmax2(x1, x3));
        __half2 e0 = col[0][0], e1 = col[5][0];
        w[0][1] = __hmax2(T1, e0); w[0][0] = __hmax2(T2, __hmin2(T1, e0));
        w[1][1] = __hmax2(T1, e1); w[1][0] = __hmax2(T2, __hmin2(T1, e1));
    }
    // ---- Row 1: top-3 set of 5. ----
    {
        __half2 x1 = col[1][1], x2 = col[2][1], x3 = col[3][1], x4 = col[4][1];
        cas2(x1, x2); cas2(x3, x4);
        __half2 y  = __hmax2(x1, x3);
        __half2 mx = __hmax2(x2, x4), mn = __hmin2(x2, x4);
        __half2 e0 = col[0][1], e1 = col[5][1];
        w[0][2] = mx; w[0][3] = __hmax2(y, e0); w[0][4] = __hmax2(mn, __hmin2(y, e0));
        w[1][2] = mx; w[1][3] = __hmax2(y, e1); w[1][4] = __hmax2(mn, __hmin2(y, e1));
    }
    // ---- Row 2 (column medians): middle-3 set of 5. ----
    {
        __half2 x1 = col[1][2], x2 = col[2][2], x3 = col[3][2], x4 = col[4][2];
        cas2(x1, x2); cas2(x3, x4); cas2(x1, x3); cas2(x2, x4);
        __half2 e0 = col[0][2], e1 = col[5][2];
        w[0][5] = x2; w[0][6] = x3; w[0][7] = __hmin2(__hmax2(x1, e0), x4);
        w[1][5] = x2; w[1][6] = x3; w[1][7] = __hmin2(__hmax2(x1, e1), x4);
    }
    // ---- Row 3: bottom-3 set of 5. ----
    {
        __half2 x1 = col[1][3], x2 = col[2][3], x3 = col[3][3], x4 = col[4][3];
        cas2(x1, x2); cas2(x3, x4);
        __half2 z = __hmin2(x2, x4);
        __half2 m = __hmin2(x1, x3), M = __hmax2(x1, x3);
        __half2 e0 = col[0][3], e1 = col[5][3];
        s[0][0] = m; s[0][1] = __hmin2(z, e0); s[0][2] = __hmin2(M, __hmax2(z, e0));
        s[1][0] = m; s[1][1] = __hmin2(z, e1); s[1][2] = __hmin2(M, __hmax2(z, e1));
    }
    // ---- Row 4 (column maxima): bottom-2 set of 5. ----
    {
        __half2 x1 = col[1][4], x2 = col[2][4], x3 = col[3][4], x4 = col[4][4];
        cas2(x1, x2); cas2(x3, x4);
        __half2 B1 = __hmin2(x1, x3);
        __half2 B2 = __hmin2(__hmax2(x1, x3), __hmin2(x2, x4));
        __half2 e0 = col[0][4], e1 = col[5][4];
        s[0][3] = __hmin2(B1, e0); s[0][4] = __hmin2(B2, __hmax2(B1, e0));
        s[1][3] = __hmin2(B1, e1); s[1][4] = __hmin2(B2, __hmax2(B1, e1));
    }

    // Forgetful selection: median = rank 7 (1-indexed) of the 13 candidates.
    __half2 res[2];
    #pragma unroll
    for (int g = 0; g < 2; g++) {
        __half2 w0 = w[g][0], w1 = w[g][1], w2 = w[g][2], w3 = w[g][3];
        __half2 w4 = w[g][4], w5 = w[g][5], w6 = w[g][6], w7 = w[g][7];

        // minmax8 (tree); (w0,w1) pre-ordered (w0<=w1), first CAS elided.
        cas2(w2, w3); cas2(w4, w5); cas2(w6, w7);
        cas2(w0, w2); cas2(w4, w6); cas2(w0, w4);
        cas2(w1, w3); cas2(w5, w7); cas2(w3, w7);
        w0 = s[g][0];
        // minmax7: survivors w1..w5.
        cas2(w0, w1); cas2(w2, w3); cas2(w4, w5);
        cas2(w0, w2); cas2(w4, w6); cas2(w0, w4);
        cas2(w1, w3); cas2(w5, w6); cas2(w3, w6);
        w0 = s[g][1];
        // minmax6: survivors w1..w4.
        cas2(w0, w1); cas2(w2, w3); cas2(w4, w5);
        cas2(w0, w2); cas2(w0, w4);
        cas2(w1, w3); cas2(w3, w5);
        w0 = s[g][2];
        // minmax5: survivors w1, w2, w4.
        cas2(w0, w1); cas2(w2, w3); cas2(w0, w2); cas2(w1, w3); cas2(w0, w4); cas2(w4, w3);
        w0 = s[g][3];
        // minmax4 on (w0, w1, w2, w4): survivors w1, w2.
        cas2(w0, w1); cas2(w2, w4); cas2(w0, w2); cas2(w1, w4);
        // med3(s4, w1, w2) via 4-op identity.
        __half2 a = s[g][4];
        res[g] = __hmax2(__hmin2(a, w1), __hmin2(__hmax2(a, w1), w2));
    }

    // Unpack: pair0 = pixels (0,2), pair1 = pixels (1,3).
    float2 p0 = __half22float2(res[0]);
    float2 p1 = __half22float2(res[1]);
    float4 r4 = make_float4(p0.x, p1.x, p0.y, p1.y);

    const int gy = by + threadIdx.y;
    *reinterpret_cast<float4*>(&dst[gy * IMG + bx + threadIdx.x * PPT]) = r4;
}

extern "C" void kernel_launch(void* const* d_in, const int* in_sizes, int n_in,
                              void* d_out, int out_size) {
    const float* image = (const float*)d_in[0];
    float* out = (float*)d_out;
    (void)in_sizes; (void)n_in; (void)out_size;

    dim3 block(BX, BY);
    dim3 grid(IMG / OUT_W, IMG / OUT_H, 16 * 3);
    median5_kernel<<<grid, block>>>(image, out);
}